// round 13
// baseline (speedup 1.0000x reference)
#include <cuda_runtime.h>
#include <cuda_bf16.h>
#include <cuda_fp16.h>

#define Bd   4096
#define Sd   512
#define Ad   64
#define H1d  1024
#define H2d  512
#define EPSf 1e-8f
#define TK   16

typedef unsigned long long ull;
typedef unsigned int u32;

// ------------------------- device scratch (no allocs allowed) --------------
__device__ float g_G[Bd * H1d];              // Gp[b][o] = G*invn[b] + b1[o]
__device__ __half g_AWTh[H1d * Ad];          // [o][a] fp16 (coalesced, cp.async)
__device__ float g_invn[Bd];
__device__ __half g_W2h[H2d * H1d];          // fp16(W2)

// ------------------------- helpers -----------------------------------------
__device__ __forceinline__ u32 smem_u32(const void* p) {
    u32 a;
    asm("{ .reg .u64 t; cvta.to.shared.u64 t, %1; cvt.u32.u64 %0, t; }"
        : "=r"(a) : "l"(p));
    return a;
}
__device__ __forceinline__ ull pk2(float lo, float hi) {
    ull r;
    asm("mov.b64 %0, {%1, %2};" : "=l"(r)
        : "r"(__float_as_uint(lo)), "r"(__float_as_uint(hi)));
    return r;
}
__device__ __forceinline__ void upk2(ull v, float& lo, float& hi) {
    unsigned a, b;
    asm("mov.b64 {%0, %1}, %2;" : "=r"(a), "=r"(b) : "l"(v));
    lo = __uint_as_float(a); hi = __uint_as_float(b);
}
__device__ __forceinline__ ull ffma2(ull a, ull b, ull c) {
    ull d;
    asm("fma.rn.f32x2 %0, %1, %2, %3;" : "=l"(d) : "l"(a), "l"(b), "l"(c));
    return d;
}
// pack two f32 into f16x2 (lo -> low 16 bits)
__device__ __forceinline__ u32 pkhf(float lo, float hi) {
    u32 r;
    asm("cvt.rn.f16x2.f32 %0, %1, %2;" : "=r"(r) : "f"(hi), "f"(lo));
    return r;
}

__device__ __forceinline__ void cpasync16(u32 dst, const void* src) {
    asm volatile("cp.async.cg.shared.global [%0], [%1], 16;"
                 :: "r"(dst), "l"(src) : "memory");
}
__device__ __forceinline__ void ldm4(u32* r, u32 addr) {
    asm volatile("ldmatrix.sync.aligned.m8n8.x4.shared.b16 {%0,%1,%2,%3}, [%4];"
                 : "=r"(r[0]), "=r"(r[1]), "=r"(r[2]), "=r"(r[3]) : "r"(addr));
}
__device__ __forceinline__ void mma16816(float* c, const u32* a, u32 b0, u32 b1) {
    asm volatile(
        "mma.sync.aligned.m16n8k16.row.col.f32.f16.f16.f32 "
        "{%0,%1,%2,%3}, {%4,%5,%6,%7}, {%8,%9}, {%0,%1,%2,%3};"
        : "+f"(c[0]), "+f"(c[1]), "+f"(c[2]), "+f"(c[3])
        : "r"(a[0]), "r"(a[1]), "r"(a[2]), "r"(a[3]), "r"(b0), "r"(b1));
}

// 128B-row SW128 tile addressing: row has 8 16B k-groups
__device__ __forceinline__ u32 toff(int row, int g) {
    return (u32)(row * 128 + ((g ^ (row & 7)) << 4));
}

// ---------------------------------------------------------------------------
// Prep (merged): AWT fp16 gather + W2 fp16 convert
// ---------------------------------------------------------------------------
__global__ void k_prep(const float* __restrict__ W1,
                       const float* __restrict__ W2) {
    int i = blockIdx.x * 256 + threadIdx.x;
    if (i < H1d * Ad) {
        int o = i >> 6, a = i & 63;
        g_AWTh[i] = __float2half_rn(W1[o * 576 + 512 + a]);
    }
    int j = i - H1d * Ad;
    if (j >= 0 && j < H2d * H1d) {
        g_W2h[j] = __float2half_rn(W2[j]);
    }
}
__global__ void k_invn(const float* __restrict__ states) {
    int w    = (blockIdx.x * blockDim.x + threadIdx.x) >> 5;
    int lane = threadIdx.x & 31;
    if (w >= Bd) return;
    const float* s = states + w * Sd;
    float acc = 0.f;
#pragma unroll 4
    for (int j = lane; j < Sd; j += 32) { float v = s[j]; acc += v * v; }
#pragma unroll
    for (int off = 16; off; off >>= 1) acc += __shfl_xor_sync(0xffffffffu, acc, off);
    if (lane == 0) g_invn[w] = 1.f / (sqrtf(acc + 1.f) + EPSf);
}

// ---------------------------------------------------------------------------
// Gp[b][o] = (states[b,:].W1[o,:512]) * invn[b] + b1[o]   (fp32 SIMT)
// ---------------------------------------------------------------------------
__global__ void __launch_bounds__(256) k_gemmG(const float* __restrict__ states,
                                               const float* __restrict__ W1,
                                               const float* __restrict__ b1) {
    __shared__ __align__(16) float As[2][TK][128];
    __shared__ __align__(16) float Bs[2][TK][128];

    int b0  = (blockIdx.x >> 3) * 128;
    int o0  = (blockIdx.x & 7) * 128;
    int tid = threadIdx.x;
    int tm  = tid >> 4, tn = tid & 15;

    ull acc[4][8];
#pragma unroll
    for (int i = 0; i < 4; i++)
#pragma unroll
        for (int j = 0; j < 8; j++) acc[i][j] = 0ull;

    auto loadTile = [&](int c, int buf) {
        int k0 = c * TK;
#pragma unroll
        for (int it = 0; it < 2; it++) {
            int e = tid + it * 256;
            int r = e >> 2, kq = (e & 3) * 4;
            float4 va = *(const float4*)&states[(b0 + r) * Sd + k0 + kq];
            As[buf][kq + 0][r] = va.x; As[buf][kq + 1][r] = va.y;
            As[buf][kq + 2][r] = va.z; As[buf][kq + 3][r] = va.w;
            float4 vb = *(const float4*)&W1[(o0 + r) * 576 + k0 + kq];
            Bs[buf][kq + 0][r] = vb.x; Bs[buf][kq + 1][r] = vb.y;
            Bs[buf][kq + 2][r] = vb.z; Bs[buf][kq + 3][r] = vb.w;
        }
    };

    loadTile(0, 0);
    __syncthreads();
    const int NC = Sd / TK;
    for (int c = 0; c < NC; c++) {
        int buf = c & 1;
        if (c + 1 < NC) loadTile(c + 1, buf ^ 1);
#pragma unroll
        for (int kk = 0; kk < TK; kk++) {
            ull a2[4];
            const ull* ap = (const ull*)&As[buf][kk][tm * 8];
#pragma unroll
            for (int i = 0; i < 4; i++) a2[i] = ap[i];
            float4 bv0 = *(const float4*)&Bs[buf][kk][tn * 8];
            float4 bv1 = *(const float4*)&Bs[buf][kk][tn * 8 + 4];
            ull b2r[8];
            b2r[0] = pk2(bv0.x, bv0.x); b2r[1] = pk2(bv0.y, bv0.y);
            b2r[2] = pk2(bv0.z, bv0.z); b2r[3] = pk2(bv0.w, bv0.w);
            b2r[4] = pk2(bv1.x, bv1.x); b2r[5] = pk2(bv1.y, bv1.y);
            b2r[6] = pk2(bv1.z, bv1.z); b2r[7] = pk2(bv1.w, bv1.w);
#pragma unroll
            for (int i = 0; i < 4; i++)
#pragma unroll
                for (int j = 0; j < 8; j++)
                    acc[i][j] = ffma2(a2[i], b2r[j], acc[i][j]);
        }
        __syncthreads();
    }

    float4 b1a = *(const float4*)&b1[o0 + tn * 8];
    float4 b1b = *(const float4*)&b1[o0 + tn * 8 + 4];
    float bb[8] = {b1a.x, b1a.y, b1a.z, b1a.w, b1b.x, b1b.y, b1b.z, b1b.w};
#pragma unroll
    for (int i = 0; i < 4; i++) {
        int m0 = b0 + tm * 8 + i * 2;
        float inv0 = g_invn[m0], inv1 = g_invn[m0 + 1];
        float lo[8], hi[8];
#pragma unroll
        for (int j = 0; j < 8; j++) {
            upk2(acc[i][j], lo[j], hi[j]);
            lo[j] = fmaf(lo[j], inv0, bb[j]);
            hi[j] = fmaf(hi[j], inv1, bb[j]);
        }
        float* p0 = &g_G[(m0 + 0) * H1d + o0 + tn * 8];
        float* p1 = &g_G[(m0 + 1) * H1d + o0 + tn * 8];
        *(float4*)p0       = make_float4(lo[0], lo[1], lo[2], lo[3]);
        *(float4*)(p0 + 4) = make_float4(lo[4], lo[5], lo[6], lo[7]);
        *(float4*)p1       = make_float4(hi[0], hi[1], hi[2], hi[3]);
        *(float4*)(p1 + 4) = make_float4(hi[4], hi[5], hi[6], hi[7]);
    }
}

// ---------------------------------------------------------------------------
// Main fused kernel: M=64 rows/CTA, N=512 in 2 passes of 256, K=1024 in
// 16 chunks of 64. A = single fp16 (scaled by 64), B = fp16. 2 CTAs/SM.
// AWT staged via cp.async; B fragments pipelined two-deep inside each ks.
// ---------------------------------------------------------------------------
#define SOFF_GPS   0        // 1024 f32 (4 KB), pre-scaled by 64
#define SOFF_B2    4096     // 512 f32
#define SOFF_WQ    6144     // 512 f32
#define SOFF_SS    8192     // 256 f32 (ss; reused for q cross-warp partials)
#define SOFF_RINV  9216     // 64 f32
#define SOFF_AWT   10240    // 2 slots x 8 KB (64 o-rows x 64 a fp16)
#define SOFF_STG   26624
#define AF_OFF     0        // 64 rows x 128B = 8 KB
#define BF_OFF     8192     // 256 rows x 128B = 32 KB
#define STG_BYTES  40960    // 40 KB per stage
#define SMEM_TOTAL (SOFF_STG + 2 * STG_BYTES)   // 108544 B -> 2 CTAs = 212 KB

#define KC  64
#define NCH (H1d / KC)      // 16 chunks per pass
#define ASCALE 64.0f

__global__ void __launch_bounds__(256, 2)
k_main(const float* __restrict__ b2, const float* __restrict__ Wq,
       const float* __restrict__ bq, float* __restrict__ out) {
    extern __shared__ __align__(1024) char smem[];
    u32 sb = smem_u32(smem);
    int tid = threadIdx.x;
    int wid = tid >> 5, lane = tid & 31;
    int warp_m = wid >> 2, warp_n = wid & 3;       // 2 x 4 warp grid
    int bidx = blockIdx.x;                          // 1 batch row per CTA
    int r0 = bidx * 64;

    float* Gps   = (float*)(smem + SOFF_GPS);
    float* b2s   = (float*)(smem + SOFF_B2);
    float* wqs   = (float*)(smem + SOFF_WQ);
    float* sss   = (float*)(smem + SOFF_SS);
    float* rinvs = (float*)(smem + SOFF_RINV);

    // Gps pre-scaled by ASCALE so generated h is 64x the true h1
    float inv = g_invn[bidx] * ASCALE;
    for (int i = tid; i < H1d; i += 256)
        Gps[i] = g_G[(size_t)bidx * H1d + i] * ASCALE;
    for (int i = tid; i < H2d; i += 256) { b2s[i] = b2[i]; wqs[i] = Wq[i]; }
    __syncthreads();

    // generator identity: row gm (0..63 = action), k-group pair gq2 (0..3)
    int gm = tid & 63, gq2 = tid >> 6;
    float ss = 0.f;

    // AWT slice loader: chunk c (64 o-rows x 64 a fp16 = 8 KB), contiguous
    auto loadAWT = [&](int c, int slot) {
        u32 dst = sb + SOFF_AWT + slot * 8192;
        const __half* src = g_AWTh + (size_t)c * KC * Ad;
#pragma unroll
        for (int i = 0; i < 2; i++) {
            int e = tid + i * 256;
            cpasync16(dst + e * 16, src + e * 8);
        }
    };

    // A generator piece: 8 k-values (group g = gq2*2 + piece); AWT via LDS
    auto genAp = [&](int c, int buf, int piece, bool do_ss) {
        char* stg = smem + SOFF_STG + buf * STG_BYTES;
        const __half* awts = (const __half*)(smem + SOFF_AWT + (c & 1) * 8192);
        int g = gq2 * 2 + piece;
        int ol = g * 8;                 // chunk-local o
        int o = c * KC + ol;            // global o
        float h[8];
#pragma unroll
        for (int j = 0; j < 8; j++) {
            float w = __half2float(awts[(ol + j) * Ad + gm]);
            h[j] = fmaxf(fmaf(inv, w, Gps[o + j]), 0.f);
        }
        if (do_ss) {
            float s2 = 0.f;
#pragma unroll
            for (int j = 0; j < 8; j++) s2 = fmaf(h[j], h[j], s2);
            ss += s2;
        }
        u32 q0 = pkhf(h[0], h[1]), q1 = pkhf(h[2], h[3]);
        u32 q2 = pkhf(h[4], h[5]), q3 = pkhf(h[6], h[7]);
        *(uint4*)(stg + AF_OFF + toff(gm, g)) = make_uint4(q0, q1, q2, q3);
    };

    // B loader: W2 fp16, 256 n-rows x 64 k per chunk
    auto loadB = [&](int pass, int c, int buf) {
        u32 bf = sb + SOFF_STG + buf * STG_BYTES + BF_OFF;
        const __half* w2 = g_W2h + (size_t)(pass * 256) * H1d + c * KC;
#pragma unroll
        for (int i = 0; i < 8; i++) {
            int e = tid + i * 256;
            int n = e >> 3, g = e & 7;
            cpasync16(bf + toff(n, g), w2 + (size_t)n * H1d + g * 8);
        }
    };

    int lt = lane & 15, lh = lane >> 4;
    float qacc[4] = {0.f, 0.f, 0.f, 0.f};

    for (int pass = 0; pass < 2; pass++) {
        float acc[2][8][4];
#pragma unroll
        for (int i = 0; i < 2; i++)
#pragma unroll
            for (int j = 0; j < 8; j++)
#pragma unroll
                for (int k = 0; k < 4; k++) acc[i][j][k] = 0.f;

        // prologue: AWT(0) first group; B(0)+AWT(1) second group
        loadAWT(0, 0);
        asm volatile("cp.async.commit_group;" ::: "memory");
        loadB(pass, 0, 0);
        loadAWT(1, 1);
        asm volatile("cp.async.commit_group;" ::: "memory");
        asm volatile("cp.async.wait_group 1;" ::: "memory");   // AWT(0) ready
        __syncthreads();
        genAp(0, 0, 0, pass == 0);
        genAp(0, 0, 1, pass == 0);
        asm volatile("cp.async.wait_group 0;" ::: "memory");
        __syncthreads();

        for (int c = 0; c < NCH; c++) {
            int buf = c & 1;
            bool more = (c + 1 < NCH);
            if (more) {
                loadB(pass, c + 1, buf ^ 1);
                if (c + 2 < NCH) loadAWT(c + 2, (c + 2) & 1);
                asm volatile("cp.async.commit_group;" ::: "memory");
            }

            u32 abase = sb + SOFF_STG + buf * STG_BYTES;
#pragma unroll
            for (int ks = 0; ks < 4; ks++) {
                // genA for next chunk first: its LDS/FMA chain overlaps
                // with the ldsm fills below
                if (more && (ks & 1) == 0)
                    genAp(c + 1, buf ^ 1, ks >> 1, pass == 0);

                int g = ks * 2 + lh;
                u32 ah[2][4];
#pragma unroll
                for (int mt = 0; mt < 2; mt++) {
                    int row = warp_m * 32 + mt * 16 + lt;
                    ldm4(ah[mt], abase + AF_OFF + toff(row, g));
                }
                // two-deep pipelined B fragments
                u32 bhA[4], bhB[4];
                {
                    int nrow0 = warp_n * 64 + 0 * 16 + lt;
                    int nrow1 = warp_n * 64 + 1 * 16 + lt;
                    ldm4(bhA, abase + BF_OFF + toff(nrow0, g));
                    ldm4(bhB, abase + BF_OFF + toff(nrow1, g));
                }
                // nb = 0 (bhA), then refill bhA with nb=2
#pragma unroll
                for (int mt = 0; mt < 2; mt++)
#pragma unroll
                    for (int s = 0; s < 2; s++)
                        mma16816(acc[mt][0 + s], ah[mt], bhA[s], bhA[s + 2]);
                {
                    int nrow2 = warp_n * 64 + 2 * 16 + lt;
                    ldm4(bhA, abase + BF_OFF + toff(nrow2, g));
                }
                // nb = 1 (bhB), then refill bhB with nb=3
#pragma unroll
                for (int mt = 0; mt < 2; mt++)
#pragma unroll
                    for (int s = 0; s < 2; s++)
                        mma16816(acc[mt][2 + s], ah[mt], bhB[s], bhB[s + 2]);
                {
                    int nrow3 = warp_n * 64 + 3 * 16 + lt;
                    ldm4(bhB, abase + BF_OFF + toff(nrow3, g));
                }
                // nb = 2 (bhA)
#pragma unroll
                for (int mt = 0; mt < 2; mt++)
#pragma unroll
                    for (int s = 0; s < 2; s++)
                        mma16816(acc[mt][4 + s], ah[mt], bhA[s], bhA[s + 2]);
                // nb = 3 (bhB)
#pragma unroll
                for (int mt = 0; mt < 2; mt++)
#pragma unroll
                    for (int s = 0; s < 2; s++)
                        mma16816(acc[mt][6 + s], ah[mt], bhB[s], bhB[s + 2]);
            }
            asm volatile("cp.async.wait_group 0;" ::: "memory");
            __syncthreads();
        }

        if (pass == 0) {
            // rinv embeds the 1/ASCALE un-scale: acc = 64*z2_pre,
            // sqrt(ss) = 64*||h||  =>  acc * rinv = z2_normalized
            sss[tid] = ss;
            __syncthreads();
            if (tid < 64)
                rinvs[tid] = 1.f / (sqrtf(sss[tid] + sss[tid + 64] +
                                          sss[tid + 128] + sss[tid + 192]) +
                                    ASCALE * EPSf);
            __syncthreads();
        }

        // epilogue: q += relu(acc * rinv + b2) * Wq for this pass's 256 n
#pragma unroll
        for (int mt = 0; mt < 2; mt++) {
            int rlo = warp_m * 32 + mt * 16 + (lane >> 2);
            float rv0 = rinvs[rlo], rv1 = rinvs[rlo + 8];
#pragma unroll
            for (int nt = 0; nt < 8; nt++) {
                int n = pass * 256 + warp_n * 64 + nt * 8 + (lane & 3) * 2;
                float bb0 = b2s[n], bb1 = b2s[n + 1];
                float w0 = wqs[n], w1 = wqs[n + 1];
                const float* cc = acc[mt][nt];
                qacc[mt * 2 + 0] += fmaxf(fmaf(cc[0], rv0, bb0), 0.f) * w0 +
                                    fmaxf(fmaf(cc[1], rv0, bb1), 0.f) * w1;
                qacc[mt * 2 + 1] += fmaxf(fmaf(cc[2], rv1, bb0), 0.f) * w0 +
                                    fmaxf(fmaf(cc[3], rv1, bb1), 0.f) * w1;
            }
        }
    }

    // reduce q over the 4 lanes of each quad
#pragma unroll
    for (int off = 1; off <= 2; off <<= 1)
#pragma unroll
        for (int i = 0; i < 4; i++)
            qacc[i] += __shfl_xor_sync(0xffffffffu, qacc[i], off);

    __syncthreads();          // reuse sss for q cross-warp partials (256 f32)
    if ((lane & 3) == 0) {
#pragma unroll
        for (int mt = 0; mt < 2; mt++)
#pragma unroll
            for (int hh = 0; hh < 2; hh++) {
                int row = warp_m * 32 + mt * 16 + hh * 8 + (lane >> 2);
                sss[row * 4 + warp_n] = qacc[mt * 2 + hh];
            }
    }
    __syncthreads();
    if (tid < 64)
        out[r0 + tid] = sss[tid * 4] + sss[tid * 4 + 1] +
                        sss[tid * 4 + 2] + sss[tid * 4 + 3] + __ldg(bq);
}

// ---------------------------------------------------------------------------
extern "C" void kernel_launch(void* const* d_in, const int* in_sizes, int n_in,
                              void* d_out, int out_size) {
    const float* states = (const float*)d_in[0];
    const float* W1     = (const float*)d_in[1];
    const float* b1     = (const float*)d_in[2];
    const float* W2     = (const float*)d_in[3];
    const float* b2     = (const float*)d_in[4];
    const float* Wq     = (const float*)d_in[5];
    const float* bq     = (const float*)d_in[6];
    float* out = (float*)d_out;

    cudaFuncSetAttribute((const void*)k_main,
                         cudaFuncAttributeMaxDynamicSharedMemorySize, SMEM_TOTAL);

    k_invn<<<Bd / 8, 256>>>(states);
    k_prep<<<(H1d * Ad + H2d * H1d + 255) / 256, 256>>>(W1, W2);
    k_gemmG<<<(Bd / 128) * (H1d / 128), 256>>>(states, W1, b1);
    k_main<<<Bd, 256, SMEM_TOTAL>>>(b2, Wq, bq, out);
}

// round 14
// speedup vs baseline: 1.0073x; 1.0073x over previous
#include <cuda_runtime.h>
#include <cuda_bf16.h>
#include <cuda_fp16.h>

#define Bd   4096
#define Sd   512
#define Ad   64
#define H1d  1024
#define H2d  512
#define EPSf 1e-8f
#define TK   16

typedef unsigned long long ull;
typedef unsigned int u32;

// ------------------------- device scratch (no allocs allowed) --------------
__device__ float g_G[Bd * H1d];              // Gp[b][o] = G*invn[b] + b1[o]
__device__ __half g_AWTt2[Ad * H1d];         // [a][o] fp16 (row-contig slices)
__device__ float g_invn[Bd];
__device__ __half g_W2h[H2d * H1d];          // fp16(W2)

// ------------------------- helpers -----------------------------------------
__device__ __forceinline__ u32 smem_u32(const void* p) {
    u32 a;
    asm("{ .reg .u64 t; cvta.to.shared.u64 t, %1; cvt.u32.u64 %0, t; }"
        : "=r"(a) : "l"(p));
    return a;
}
__device__ __forceinline__ ull pk2(float lo, float hi) {
    ull r;
    asm("mov.b64 %0, {%1, %2};" : "=l"(r)
        : "r"(__float_as_uint(lo)), "r"(__float_as_uint(hi)));
    return r;
}
__device__ __forceinline__ void upk2(ull v, float& lo, float& hi) {
    unsigned a, b;
    asm("mov.b64 {%0, %1}, %2;" : "=r"(a), "=r"(b) : "l"(v));
    lo = __uint_as_float(a); hi = __uint_as_float(b);
}
__device__ __forceinline__ ull ffma2(ull a, ull b, ull c) {
    ull d;
    asm("fma.rn.f32x2 %0, %1, %2, %3;" : "=l"(d) : "l"(a), "l"(b), "l"(c));
    return d;
}
// pack two f32 into f16x2 (lo -> low 16 bits)
__device__ __forceinline__ u32 pkhf(float lo, float hi) {
    u32 r;
    asm("cvt.rn.f16x2.f32 %0, %1, %2;" : "=r"(r) : "f"(hi), "f"(lo));
    return r;
}

__device__ __forceinline__ void cpasync16(u32 dst, const void* src) {
    asm volatile("cp.async.cg.shared.global [%0], [%1], 16;"
                 :: "r"(dst), "l"(src) : "memory");
}
__device__ __forceinline__ void ldm4(u32* r, u32 addr) {
    asm volatile("ldmatrix.sync.aligned.m8n8.x4.shared.b16 {%0,%1,%2,%3}, [%4];"
                 : "=r"(r[0]), "=r"(r[1]), "=r"(r[2]), "=r"(r[3]) : "r"(addr));
}
__device__ __forceinline__ void mma16816(float* c, const u32* a, u32 b0, u32 b1) {
    asm volatile(
        "mma.sync.aligned.m16n8k16.row.col.f32.f16.f16.f32 "
        "{%0,%1,%2,%3}, {%4,%5,%6,%7}, {%8,%9}, {%0,%1,%2,%3};"
        : "+f"(c[0]), "+f"(c[1]), "+f"(c[2]), "+f"(c[3])
        : "r"(a[0]), "r"(a[1]), "r"(a[2]), "r"(a[3]), "r"(b0), "r"(b1));
}

// 128B-row SW128 tile addressing: row has 8 16B k-groups
__device__ __forceinline__ u32 toff(int row, int g) {
    return (u32)(row * 128 + ((g ^ (row & 7)) << 4));
}

// ---------------------------------------------------------------------------
// Prep (merged): AWT a-major fp16 gather + W2 fp16 convert
// ---------------------------------------------------------------------------
__global__ void k_prep(const float* __restrict__ W1,
                       const float* __restrict__ W2) {
    int i = blockIdx.x * 256 + threadIdx.x;
    if (i < Ad * H1d) {
        int a = i >> 10, o = i & 1023;
        g_AWTt2[i] = __float2half_rn(W1[o * 576 + 512 + a]);
    }
    int j = i - Ad * H1d;
    if (j >= 0 && j < H2d * H1d) {
        g_W2h[j] = __float2half_rn(W2[j]);
    }
}
__global__ void k_invn(const float* __restrict__ states) {
    int w    = (blockIdx.x * blockDim.x + threadIdx.x) >> 5;
    int lane = threadIdx.x & 31;
    if (w >= Bd) return;
    const float* s = states + w * Sd;
    float acc = 0.f;
#pragma unroll 4
    for (int j = lane; j < Sd; j += 32) { float v = s[j]; acc += v * v; }
#pragma unroll
    for (int off = 16; off; off >>= 1) acc += __shfl_xor_sync(0xffffffffu, acc, off);
    if (lane == 0) g_invn[w] = 1.f / (sqrtf(acc + 1.f) + EPSf);
}

// ---------------------------------------------------------------------------
// Gp[b][o] = (states[b,:].W1[o,:512]) * invn[b] + b1[o]   (fp32 SIMT)
// ---------------------------------------------------------------------------
__global__ void __launch_bounds__(256) k_gemmG(const float* __restrict__ states,
                                               const float* __restrict__ W1,
                                               const float* __restrict__ b1) {
    __shared__ __align__(16) float As[2][TK][128];
    __shared__ __align__(16) float Bs[2][TK][128];

    int b0  = (blockIdx.x >> 3) * 128;
    int o0  = (blockIdx.x & 7) * 128;
    int tid = threadIdx.x;
    int tm  = tid >> 4, tn = tid & 15;

    ull acc[4][8];
#pragma unroll
    for (int i = 0; i < 4; i++)
#pragma unroll
        for (int j = 0; j < 8; j++) acc[i][j] = 0ull;

    auto loadTile = [&](int c, int buf) {
        int k0 = c * TK;
#pragma unroll
        for (int it = 0; it < 2; it++) {
            int e = tid + it * 256;
            int r = e >> 2, kq = (e & 3) * 4;
            float4 va = *(const float4*)&states[(b0 + r) * Sd + k0 + kq];
            As[buf][kq + 0][r] = va.x; As[buf][kq + 1][r] = va.y;
            As[buf][kq + 2][r] = va.z; As[buf][kq + 3][r] = va.w;
            float4 vb = *(const float4*)&W1[(o0 + r) * 576 + k0 + kq];
            Bs[buf][kq + 0][r] = vb.x; Bs[buf][kq + 1][r] = vb.y;
            Bs[buf][kq + 2][r] = vb.z; Bs[buf][kq + 3][r] = vb.w;
        }
    };

    loadTile(0, 0);
    __syncthreads();
    const int NC = Sd / TK;
    for (int c = 0; c < NC; c++) {
        int buf = c & 1;
        if (c + 1 < NC) loadTile(c + 1, buf ^ 1);
#pragma unroll
        for (int kk = 0; kk < TK; kk++) {
            ull a2[4];
            const ull* ap = (const ull*)&As[buf][kk][tm * 8];
#pragma unroll
            for (int i = 0; i < 4; i++) a2[i] = ap[i];
            float4 bv0 = *(const float4*)&Bs[buf][kk][tn * 8];
            float4 bv1 = *(const float4*)&Bs[buf][kk][tn * 8 + 4];
            ull b2r[8];
            b2r[0] = pk2(bv0.x, bv0.x); b2r[1] = pk2(bv0.y, bv0.y);
            b2r[2] = pk2(bv0.z, bv0.z); b2r[3] = pk2(bv0.w, bv0.w);
            b2r[4] = pk2(bv1.x, bv1.x); b2r[5] = pk2(bv1.y, bv1.y);
            b2r[6] = pk2(bv1.z, bv1.z); b2r[7] = pk2(bv1.w, bv1.w);
#pragma unroll
            for (int i = 0; i < 4; i++)
#pragma unroll
                for (int j = 0; j < 8; j++)
                    acc[i][j] = ffma2(a2[i], b2r[j], acc[i][j]);
        }
        __syncthreads();
    }

    float4 b1a = *(const float4*)&b1[o0 + tn * 8];
    float4 b1b = *(const float4*)&b1[o0 + tn * 8 + 4];
    float bb[8] = {b1a.x, b1a.y, b1a.z, b1a.w, b1b.x, b1b.y, b1b.z, b1b.w};
#pragma unroll
    for (int i = 0; i < 4; i++) {
        int m0 = b0 + tm * 8 + i * 2;
        float inv0 = g_invn[m0], inv1 = g_invn[m0 + 1];
        float lo[8], hi[8];
#pragma unroll
        for (int j = 0; j < 8; j++) {
            upk2(acc[i][j], lo[j], hi[j]);
            lo[j] = fmaf(lo[j], inv0, bb[j]);
            hi[j] = fmaf(hi[j], inv1, bb[j]);
        }
        float* p0 = &g_G[(m0 + 0) * H1d + o0 + tn * 8];
        float* p1 = &g_G[(m0 + 1) * H1d + o0 + tn * 8];
        *(float4*)p0       = make_float4(lo[0], lo[1], lo[2], lo[3]);
        *(float4*)(p0 + 4) = make_float4(lo[4], lo[5], lo[6], lo[7]);
        *(float4*)p1       = make_float4(hi[0], hi[1], hi[2], hi[3]);
        *(float4*)(p1 + 4) = make_float4(hi[4], hi[5], hi[6], hi[7]);
    }
}

// ---------------------------------------------------------------------------
// Main fused kernel: M=64 rows/CTA, N=512 in 2 passes of 256, K=1024 in
// 16 chunks of 64. A = single fp16 (scaled by 64), B = fp16. 2 CTAs/SM.
// AWT slices staged a-major in SMEM (swizzled); genA is fully vectorized:
// 1x LDS.128 (AWT row) + 2x broadcast LDS.128 (Gps) per 8 k-values.
// ---------------------------------------------------------------------------
#define SOFF_GPS   0        // 1024 f32 (4 KB), pre-scaled by 64
#define SOFF_B2    4096     // 512 f32
#define SOFF_WQ    6144     // 512 f32
#define SOFF_SS    8192     // 256 f32 (ss; reused for q cross-warp partials)
#define SOFF_RINV  9216     // 64 f32
#define SOFF_AWT   10240    // 2 slots x 8 KB (64 a-rows x 64 o fp16, swizzled)
#define SOFF_STG   26624
#define AF_OFF     0        // 64 rows x 128B = 8 KB
#define BF_OFF     8192     // 256 rows x 128B = 32 KB
#define STG_BYTES  40960    // 40 KB per stage
#define SMEM_TOTAL (SOFF_STG + 2 * STG_BYTES)   // 108544 B -> 2 CTAs = 212 KB

#define KC  64
#define NCH (H1d / KC)      // 16 chunks per pass
#define ASCALE 64.0f

__global__ void __launch_bounds__(256, 2)
k_main(const float* __restrict__ b2, const float* __restrict__ Wq,
       const float* __restrict__ bq, float* __restrict__ out) {
    extern __shared__ __align__(1024) char smem[];
    u32 sb = smem_u32(smem);
    int tid = threadIdx.x;
    int wid = tid >> 5, lane = tid & 31;
    int warp_m = wid >> 2, warp_n = wid & 3;       // 2 x 4 warp grid
    int bidx = blockIdx.x;                          // 1 batch row per CTA
    int r0 = bidx * 64;

    float* Gps   = (float*)(smem + SOFF_GPS);
    float* b2s   = (float*)(smem + SOFF_B2);
    float* wqs   = (float*)(smem + SOFF_WQ);
    float* sss   = (float*)(smem + SOFF_SS);
    float* rinvs = (float*)(smem + SOFF_RINV);

    // Gps pre-scaled by ASCALE so generated h is 64x the true h1
    float inv = g_invn[bidx] * ASCALE;
    for (int i = tid; i < H1d; i += 256)
        Gps[i] = g_G[(size_t)bidx * H1d + i] * ASCALE;
    for (int i = tid; i < H2d; i += 256) { b2s[i] = b2[i]; wqs[i] = Wq[i]; }
    __syncthreads();

    // generator identity: row gm (0..63 = action), k-group pair gq2 (0..3)
    int gm = tid & 63, gq2 = tid >> 6;
    float ss = 0.f;

    // AWT slice loader: chunk c -> 64 a-rows x 128B (64 o fp16), swizzled.
    // src row a is contiguous: g_AWTt2[a*H1d + c*64 .. +64)
    auto loadAWT = [&](int c, int slot) {
        u32 dst = sb + SOFF_AWT + slot * 8192;
        const __half* src = g_AWTt2 + c * KC;
#pragma unroll
        for (int i = 0; i < 2; i++) {
            int e = tid + i * 256;
            int a = e >> 3, g = e & 7;
            cpasync16(dst + toff(a, g), src + (size_t)a * H1d + g * 8);
        }
    };

    // A generator piece: 8 k-values (group g = gq2*2 + piece)
    // AWT: one swizzled LDS.128 from row gm; Gps: two broadcast float4.
    auto genAp = [&](int c, int buf, int piece, bool do_ss) {
        char* stg = smem + SOFF_STG + buf * STG_BYTES;
        const char* awts = smem + SOFF_AWT + (c & 1) * 8192;
        int g = gq2 * 2 + piece;
        int o = c * KC + g * 8;         // global o (start of 8)
        uint4 wq = *(const uint4*)(awts + toff(gm, g));
        float2 w01 = __half22float2(*(const __half2*)&wq.x);
        float2 w23 = __half22float2(*(const __half2*)&wq.y);
        float2 w45 = __half22float2(*(const __half2*)&wq.z);
        float2 w67 = __half22float2(*(const __half2*)&wq.w);
        float4 gp0 = *(const float4*)&Gps[o];
        float4 gp1 = *(const float4*)&Gps[o + 4];
        float h[8];
        h[0] = fmaxf(fmaf(inv, w01.x, gp0.x), 0.f);
        h[1] = fmaxf(fmaf(inv, w01.y, gp0.y), 0.f);
        h[2] = fmaxf(fmaf(inv, w23.x, gp0.z), 0.f);
        h[3] = fmaxf(fmaf(inv, w23.y, gp0.w), 0.f);
        h[4] = fmaxf(fmaf(inv, w45.x, gp1.x), 0.f);
        h[5] = fmaxf(fmaf(inv, w45.y, gp1.y), 0.f);
        h[6] = fmaxf(fmaf(inv, w67.x, gp1.z), 0.f);
        h[7] = fmaxf(fmaf(inv, w67.y, gp1.w), 0.f);
        if (do_ss) {
            float s2 = 0.f;
#pragma unroll
            for (int j = 0; j < 8; j++) s2 = fmaf(h[j], h[j], s2);
            ss += s2;
        }
        u32 q0 = pkhf(h[0], h[1]), q1 = pkhf(h[2], h[3]);
        u32 q2 = pkhf(h[4], h[5]), q3 = pkhf(h[6], h[7]);
        *(uint4*)(stg + AF_OFF + toff(gm, g)) = make_uint4(q0, q1, q2, q3);
    };

    // B loader: W2 fp16, 256 n-rows x 64 k per chunk
    auto loadB = [&](int pass, int c, int buf) {
        u32 bf = sb + SOFF_STG + buf * STG_BYTES + BF_OFF;
        const __half* w2 = g_W2h + (size_t)(pass * 256) * H1d + c * KC;
#pragma unroll
        for (int i = 0; i < 8; i++) {
            int e = tid + i * 256;
            int n = e >> 3, g = e & 7;
            cpasync16(bf + toff(n, g), w2 + (size_t)n * H1d + g * 8);
        }
    };

    int lt = lane & 15, lh = lane >> 4;
    float qacc[4] = {0.f, 0.f, 0.f, 0.f};

    for (int pass = 0; pass < 2; pass++) {
        float acc[2][8][4];
#pragma unroll
        for (int i = 0; i < 2; i++)
#pragma unroll
            for (int j = 0; j < 8; j++)
#pragma unroll
                for (int k = 0; k < 4; k++) acc[i][j][k] = 0.f;

        // prologue: AWT(0) first group; B(0)+AWT(1) second group
        loadAWT(0, 0);
        asm volatile("cp.async.commit_group;" ::: "memory");
        loadB(pass, 0, 0);
        loadAWT(1, 1);
        asm volatile("cp.async.commit_group;" ::: "memory");
        asm volatile("cp.async.wait_group 1;" ::: "memory");   // AWT(0) ready
        __syncthreads();
        genAp(0, 0, 0, pass == 0);
        genAp(0, 0, 1, pass == 0);
        asm volatile("cp.async.wait_group 0;" ::: "memory");
        __syncthreads();

        for (int c = 0; c < NCH; c++) {
            int buf = c & 1;
            bool more = (c + 1 < NCH);
            if (more) {
                loadB(pass, c + 1, buf ^ 1);
                if (c + 2 < NCH) loadAWT(c + 2, (c + 2) & 1);
                asm volatile("cp.async.commit_group;" ::: "memory");
            }

            u32 abase = sb + SOFF_STG + buf * STG_BYTES;
#pragma unroll
            for (int ks = 0; ks < 4; ks++) {
                // interleave: generate next chunk's A tile (2 pieces)
                if (more && (ks & 1) == 0)
                    genAp(c + 1, buf ^ 1, ks >> 1, pass == 0);

                int g = ks * 2 + lh;
                u32 ah[2][4];
#pragma unroll
                for (int mt = 0; mt < 2; mt++) {
                    int row = warp_m * 32 + mt * 16 + lt;
                    ldm4(ah[mt], abase + AF_OFF + toff(row, g));
                }
#pragma unroll
                for (int nb = 0; nb < 4; nb++) {
                    int nrow = warp_n * 64 + nb * 16 + lt;
                    u32 bh[4];
                    ldm4(bh, abase + BF_OFF + toff(nrow, g));
#pragma unroll
                    for (int mt = 0; mt < 2; mt++)
#pragma unroll
                        for (int s = 0; s < 2; s++)
                            mma16816(acc[mt][nb * 2 + s], ah[mt],
                                     bh[s], bh[s + 2]);
                }
            }
            asm volatile("cp.async.wait_group 0;" ::: "memory");
            __syncthreads();
        }

        if (pass == 0) {
            // rinv embeds the 1/ASCALE un-scale: acc = 64*z2_pre,
            // sqrt(ss) = 64*||h||  =>  acc * rinv = z2_normalized
            sss[tid] = ss;
            __syncthreads();
            if (tid < 64)
                rinvs[tid] = 1.f / (sqrtf(sss[tid] + sss[tid + 64] +
                                          sss[tid + 128] + sss[tid + 192]) +
                                    ASCALE * EPSf);
            __syncthreads();
        }

        // epilogue: q += relu(acc * rinv + b2) * Wq for this pass's 256 n
#pragma unroll
        for (int mt = 0; mt < 2; mt++) {
            int rlo = warp_m * 32 + mt * 16 + (lane >> 2);
            float rv0 = rinvs[rlo], rv1 = rinvs[rlo + 8];
#pragma unroll
            for (int nt = 0; nt < 8; nt++) {
                int n = pass * 256 + warp_n * 64 + nt * 8 + (lane & 3) * 2;
                float bb0 = b2s[n], bb1 = b2s[n + 1];
                float w0 = wqs[n], w1 = wqs[n + 1];
                const float* cc = acc[mt][nt];
                qacc[mt * 2 + 0] += fmaxf(fmaf(cc[0], rv0, bb0), 0.f) * w0 +
                                    fmaxf(fmaf(cc[1], rv0, bb1), 0.f) * w1;
                qacc[mt * 2 + 1] += fmaxf(fmaf(cc[2], rv1, bb0), 0.f) * w0 +
                                    fmaxf(fmaf(cc[3], rv1, bb1), 0.f) * w1;
            }
        }
    }

    // reduce q over the 4 lanes of each quad
#pragma unroll
    for (int off = 1; off <= 2; off <<= 1)
#pragma unroll
        for (int i = 0; i < 4; i++)
            qacc[i] += __shfl_xor_sync(0xffffffffu, qacc[i], off);

    __syncthreads();          // reuse sss for q cross-warp partials (256 f32)
    if ((lane & 3) == 0) {
#pragma unroll
        for (int mt = 0; mt < 2; mt++)
#pragma unroll
            for (int hh = 0; hh < 2; hh++) {
                int row = warp_m * 32 + mt * 16 + hh * 8 + (lane >> 2);
                sss[row * 4 + warp_n] = qacc[mt * 2 + hh];
            }
    }
    __syncthreads();
    if (tid < 64)
        out[r0 + tid] = sss[tid * 4] + sss[tid * 4 + 1] +
                        sss[tid * 4 + 2] + sss[tid * 4 + 3] + __ldg(bq);
}

// ---------------------------------------------------------------------------
extern "C" void kernel_launch(void* const* d_in, const int* in_sizes, int n_in,
                              void* d_out, int out_size) {
    const float* states = (const float*)d_in[0];
    const float* W1     = (const float*)d_in[1];
    const float* b1     = (const float*)d_in[2];
    const float* W2     = (const float*)d_in[3];
    const float* b2     = (const float*)d_in[4];
    const float* Wq     = (const float*)d_in[5];
    const float* bq     = (const float*)d_in[6];
    float* out = (float*)d_out;

    cudaFuncSetAttribute((const void*)k_main,
                         cudaFuncAttributeMaxDynamicSharedMemorySize, SMEM_TOTAL);

    k_invn<<<Bd / 8, 256>>>(states);
    k_prep<<<(Ad * H1d + H2d * H1d + 255) / 256, 256>>>(W1, W2);
    k_gemmG<<<(Bd / 128) * (H1d / 128), 256>>>(states, W1, b1);
    k_main<<<Bd, 256, SMEM_TOTAL>>>(b2, Wq, bq, out);
}

// round 15
// speedup vs baseline: 1.0460x; 1.0384x over previous
#include <cuda_runtime.h>
#include <cuda_bf16.h>
#include <cuda_fp16.h>

#define Bd   4096
#define Sd   512
#define Ad   64
#define H1d  1024
#define H2d  512
#define EPSf 1e-8f
#define TK   16
#define NROWS (Bd * Ad)

typedef unsigned long long ull;
typedef unsigned int u32;

// ------------------------- device scratch (no allocs allowed) --------------
__device__ float g_G[Bd * H1d];              // 64*(G*invn + b1)  (pre-scaled)
__device__ __half g_AWTt2[Ad * H1d];         // [a][o] fp16
__device__ float g_invn[Bd];
__device__ __half g_W2h[H2d * H1d];          // fp16(W2)
__device__ __half g_h1[(size_t)NROWS * H1d]; // 512 MB: scaled fp16 h1 rows
__device__ float g_rinv[NROWS];              // 1/(||h64|| + 64*eps)

// ------------------------- helpers -----------------------------------------
__device__ __forceinline__ u32 smem_u32(const void* p) {
    u32 a;
    asm("{ .reg .u64 t; cvta.to.shared.u64 t, %1; cvt.u32.u64 %0, t; }"
        : "=r"(a) : "l"(p));
    return a;
}
__device__ __forceinline__ ull pk2(float lo, float hi) {
    ull r;
    asm("mov.b64 %0, {%1, %2};" : "=l"(r)
        : "r"(__float_as_uint(lo)), "r"(__float_as_uint(hi)));
    return r;
}
__device__ __forceinline__ void upk2(ull v, float& lo, float& hi) {
    unsigned a, b;
    asm("mov.b64 {%0, %1}, %2;" : "=r"(a), "=r"(b) : "l"(v));
    lo = __uint_as_float(a); hi = __uint_as_float(b);
}
__device__ __forceinline__ ull ffma2(ull a, ull b, ull c) {
    ull d;
    asm("fma.rn.f32x2 %0, %1, %2, %3;" : "=l"(d) : "l"(a), "l"(b), "l"(c));
    return d;
}
__device__ __forceinline__ u32 pkhf(float lo, float hi) {
    u32 r;
    asm("cvt.rn.f16x2.f32 %0, %1, %2;" : "=r"(r) : "f"(hi), "f"(lo));
    return r;
}
__device__ __forceinline__ void cpasync16(u32 dst, const void* src) {
    asm volatile("cp.async.cg.shared.global [%0], [%1], 16;"
                 :: "r"(dst), "l"(src) : "memory");
}
__device__ __forceinline__ void ldm4(u32* r, u32 addr) {
    asm volatile("ldmatrix.sync.aligned.m8n8.x4.shared.b16 {%0,%1,%2,%3}, [%4];"
                 : "=r"(r[0]), "=r"(r[1]), "=r"(r[2]), "=r"(r[3]) : "r"(addr));
}
__device__ __forceinline__ void mma16816(float* c, const u32* a, u32 b0, u32 b1) {
    asm volatile(
        "mma.sync.aligned.m16n8k16.row.col.f32.f16.f16.f32 "
        "{%0,%1,%2,%3}, {%4,%5,%6,%7}, {%8,%9}, {%0,%1,%2,%3};"
        : "+f"(c[0]), "+f"(c[1]), "+f"(c[2]), "+f"(c[3])
        : "r"(a[0]), "r"(a[1]), "r"(a[2]), "r"(a[3]), "r"(b0), "r"(b1));
}
// 128B-row SW128 tile addressing: row has 8 16B k-groups
__device__ __forceinline__ u32 toff(int row, int g) {
    return (u32)(row * 128 + ((g ^ (row & 7)) << 4));
}

// ---------------------------------------------------------------------------
// Prep: AWT a-major fp16 gather + W2 fp16 convert
// ---------------------------------------------------------------------------
__global__ void k_prep(const float* __restrict__ W1,
                       const float* __restrict__ W2) {
    int i = blockIdx.x * 256 + threadIdx.x;
    if (i < Ad * H1d) {
        int a = i >> 10, o = i & 1023;
        g_AWTt2[i] = __float2half_rn(W1[o * 576 + 512 + a]);
    }
    int j = i - Ad * H1d;
    if (j >= 0 && j < H2d * H1d) {
        g_W2h[j] = __float2half_rn(W2[j]);
    }
}
__global__ void k_invn(const float* __restrict__ states) {
    int w    = (blockIdx.x * blockDim.x + threadIdx.x) >> 5;
    int lane = threadIdx.x & 31;
    if (w >= Bd) return;
    const float* s = states + w * Sd;
    float acc = 0.f;
#pragma unroll 4
    for (int j = lane; j < Sd; j += 32) { float v = s[j]; acc += v * v; }
#pragma unroll
    for (int off = 16; off; off >>= 1) acc += __shfl_xor_sync(0xffffffffu, acc, off);
    if (lane == 0) g_invn[w] = 1.f / (sqrtf(acc + 1.f) + EPSf);
}

// ---------------------------------------------------------------------------
// g_G[b][o] = 64 * ((states[b,:].W1[o,:512]) * invn[b] + b1[o])
// ---------------------------------------------------------------------------
__global__ void __launch_bounds__(256) k_gemmG(const float* __restrict__ states,
                                               const float* __restrict__ W1,
                                               const float* __restrict__ b1) {
    __shared__ __align__(16) float As[2][TK][128];
    __shared__ __align__(16) float Bs[2][TK][128];

    int b0  = (blockIdx.x >> 3) * 128;
    int o0  = (blockIdx.x & 7) * 128;
    int tid = threadIdx.x;
    int tm  = tid >> 4, tn = tid & 15;

    ull acc[4][8];
#pragma unroll
    for (int i = 0; i < 4; i++)
#pragma unroll
        for (int j = 0; j < 8; j++) acc[i][j] = 0ull;

    auto loadTile = [&](int c, int buf) {
        int k0 = c * TK;
#pragma unroll
        for (int it = 0; it < 2; it++) {
            int e = tid + it * 256;
            int r = e >> 2, kq = (e & 3) * 4;
            float4 va = *(const float4*)&states[(b0 + r) * Sd + k0 + kq];
            As[buf][kq + 0][r] = va.x; As[buf][kq + 1][r] = va.y;
            As[buf][kq + 2][r] = va.z; As[buf][kq + 3][r] = va.w;
            float4 vb = *(const float4*)&W1[(o0 + r) * 576 + k0 + kq];
            Bs[buf][kq + 0][r] = vb.x; Bs[buf][kq + 1][r] = vb.y;
            Bs[buf][kq + 2][r] = vb.z; Bs[buf][kq + 3][r] = vb.w;
        }
    };

    loadTile(0, 0);
    __syncthreads();
    const int NC = Sd / TK;
    for (int c = 0; c < NC; c++) {
        int buf = c & 1;
        if (c + 1 < NC) loadTile(c + 1, buf ^ 1);
#pragma unroll
        for (int kk = 0; kk < TK; kk++) {
            ull a2[4];
            const ull* ap = (const ull*)&As[buf][kk][tm * 8];
#pragma unroll
            for (int i = 0; i < 4; i++) a2[i] = ap[i];
            float4 bv0 = *(const float4*)&Bs[buf][kk][tn * 8];
            float4 bv1 = *(const float4*)&Bs[buf][kk][tn * 8 + 4];
            ull b2r[8];
            b2r[0] = pk2(bv0.x, bv0.x); b2r[1] = pk2(bv0.y, bv0.y);
            b2r[2] = pk2(bv0.z, bv0.z); b2r[3] = pk2(bv0.w, bv0.w);
            b2r[4] = pk2(bv1.x, bv1.x); b2r[5] = pk2(bv1.y, bv1.y);
            b2r[6] = pk2(bv1.z, bv1.z); b2r[7] = pk2(bv1.w, bv1.w);
#pragma unroll
            for (int i = 0; i < 4; i++)
#pragma unroll
                for (int j = 0; j < 8; j++)
                    acc[i][j] = ffma2(a2[i], b2r[j], acc[i][j]);
        }
        __syncthreads();
    }

    float4 b1a = *(const float4*)&b1[o0 + tn * 8];
    float4 b1b = *(const float4*)&b1[o0 + tn * 8 + 4];
    float bb[8] = {b1a.x, b1a.y, b1a.z, b1a.w, b1b.x, b1b.y, b1b.z, b1b.w};
#pragma unroll
    for (int i = 0; i < 4; i++) {
        int m0 = b0 + tm * 8 + i * 2;
        float inv0 = g_invn[m0], inv1 = g_invn[m0 + 1];
        float lo[8], hi[8];
#pragma unroll
        for (int j = 0; j < 8; j++) {
            upk2(acc[i][j], lo[j], hi[j]);
            lo[j] = fmaf(lo[j], inv0, bb[j]) * 64.0f;
            hi[j] = fmaf(hi[j], inv1, bb[j]) * 64.0f;
        }
        float* p0 = &g_G[(m0 + 0) * H1d + o0 + tn * 8];
        float* p1 = &g_G[(m0 + 1) * H1d + o0 + tn * 8];
        *(float4*)p0       = make_float4(lo[0], lo[1], lo[2], lo[3]);
        *(float4*)(p0 + 4) = make_float4(lo[4], lo[5], lo[6], lo[7]);
        *(float4*)p1       = make_float4(hi[0], hi[1], hi[2], hi[3]);
        *(float4*)(p1 + 4) = make_float4(hi[4], hi[5], hi[6], hi[7]);
    }
}

// ---------------------------------------------------------------------------
// k_genA: one warp per (b, a) row. h64[o] = relu(g64[b][o] + 64*inv*awt[a][o])
// -> fp16 row of g_h1, plus g_rinv = 1/(||h64|| + 64*eps).
// All loads/stores fully coalesced.
// ---------------------------------------------------------------------------
__global__ void __launch_bounds__(256) k_genA() {
    int w    = (blockIdx.x * blockDim.x + threadIdx.x) >> 5;
    int lane = threadIdx.x & 31;
    if (w >= NROWS) return;
    int b = w >> 6, a = w & 63;
    float inv64 = g_invn[b] * 64.0f;
    const float*  g  = g_G + (size_t)b * H1d;
    const __half* aw = g_AWTt2 + (size_t)a * H1d;
    __half* dst = g_h1 + (size_t)w * H1d;

    float ss = 0.f;
#pragma unroll
    for (int it = 0; it < 4; it++) {
        int o = it * 256 + lane * 8;
        float4 g0 = *(const float4*)(g + o);
        float4 g1 = *(const float4*)(g + o + 4);
        uint4 wq = *(const uint4*)(aw + o);
        float2 w01 = __half22float2(*(const __half2*)&wq.x);
        float2 w23 = __half22float2(*(const __half2*)&wq.y);
        float2 w45 = __half22float2(*(const __half2*)&wq.z);
        float2 w67 = __half22float2(*(const __half2*)&wq.w);
        float h[8];
        h[0] = fmaxf(fmaf(inv64, w01.x, g0.x), 0.f);
        h[1] = fmaxf(fmaf(inv64, w01.y, g0.y), 0.f);
        h[2] = fmaxf(fmaf(inv64, w23.x, g0.z), 0.f);
        h[3] = fmaxf(fmaf(inv64, w23.y, g0.w), 0.f);
        h[4] = fmaxf(fmaf(inv64, w45.x, g1.x), 0.f);
        h[5] = fmaxf(fmaf(inv64, w45.y, g1.y), 0.f);
        h[6] = fmaxf(fmaf(inv64, w67.x, g1.z), 0.f);
        h[7] = fmaxf(fmaf(inv64, w67.y, g1.w), 0.f);
#pragma unroll
        for (int j = 0; j < 8; j++) ss = fmaf(h[j], h[j], ss);
        uint4 q;
        q.x = pkhf(h[0], h[1]); q.y = pkhf(h[2], h[3]);
        q.z = pkhf(h[4], h[5]); q.w = pkhf(h[6], h[7]);
        *(uint4*)(dst + o) = q;
    }
#pragma unroll
    for (int off = 16; off; off >>= 1) ss += __shfl_xor_sync(0xffffffffu, ss, off);
    if (lane == 0) g_rinv[w] = 1.f / (sqrtf(ss) + 64.0f * EPSf);
}

// ---------------------------------------------------------------------------
// Main kernel: pure GEMM. M=64 rows/CTA, N=512 in 2 passes of 256, K=1024
// in 16 chunks of 64. A (g_h1) and B (g_W2h) both via cp.async. 2 CTAs/SM.
// ---------------------------------------------------------------------------
#define SOFF_B2    0        // 512 f32
#define SOFF_WQ    2048     // 512 f32
#define SOFF_RINV  4096     // 64 f32
#define SOFF_SS    4352     // 256 f32 (q cross-warp partials)
#define SOFF_STG   6144
#define AF_OFF     0        // 64 rows x 128B = 8 KB
#define BF_OFF     8192     // 256 rows x 128B = 32 KB
#define STG_BYTES  40960    // 40 KB per stage
#define SMEM_TOTAL (SOFF_STG + 2 * STG_BYTES)   // 88064 B -> 2 CTAs = 172 KB

#define KC  64
#define NCH (H1d / KC)      // 16 chunks per pass

__global__ void __launch_bounds__(256, 2)
k_main(const float* __restrict__ b2, const float* __restrict__ Wq,
       const float* __restrict__ bq, float* __restrict__ out) {
    extern __shared__ __align__(1024) char smem[];
    u32 sb = smem_u32(smem);
    int tid = threadIdx.x;
    int wid = tid >> 5, lane = tid & 31;
    int warp_m = wid >> 2, warp_n = wid & 3;       // 2 x 4 warp grid
    int bidx = blockIdx.x;
    int r0 = bidx * 64;

    float* b2s   = (float*)(smem + SOFF_B2);
    float* wqs   = (float*)(smem + SOFF_WQ);
    float* rinvs = (float*)(smem + SOFF_RINV);
    float* sss   = (float*)(smem + SOFF_SS);

    for (int i = tid; i < H2d; i += 256) { b2s[i] = b2[i]; wqs[i] = Wq[i]; }
    if (tid < 64) rinvs[tid] = g_rinv[r0 + tid];
    __syncthreads();

    // A loader: 64 rows x 64 k fp16 per chunk (8 KB)
    auto loadA = [&](int c, int buf) {
        u32 af = sb + SOFF_STG + buf * STG_BYTES + AF_OFF;
        const __half* h1 = g_h1 + (size_t)r0 * H1d + c * KC;
#pragma unroll
        for (int i = 0; i < 2; i++) {
            int e = tid + i * 256;
            int row = e >> 3, g = e & 7;
            cpasync16(af + toff(row, g), h1 + (size_t)row * H1d + g * 8);
        }
    };
    // B loader: W2 fp16, 256 n-rows x 64 k per chunk (32 KB)
    auto loadB = [&](int pass, int c, int buf) {
        u32 bf = sb + SOFF_STG + buf * STG_BYTES + BF_OFF;
        const __half* w2 = g_W2h + (size_t)(pass * 256) * H1d + c * KC;
#pragma unroll
        for (int i = 0; i < 8; i++) {
            int e = tid + i * 256;
            int n = e >> 3, g = e & 7;
            cpasync16(bf + toff(n, g), w2 + (size_t)n * H1d + g * 8);
        }
    };

    int lt = lane & 15, lh = lane >> 4;
    float qacc[4] = {0.f, 0.f, 0.f, 0.f};

    for (int pass = 0; pass < 2; pass++) {
        float acc[2][8][4];
#pragma unroll
        for (int i = 0; i < 2; i++)
#pragma unroll
            for (int j = 0; j < 8; j++)
#pragma unroll
                for (int k = 0; k < 4; k++) acc[i][j][k] = 0.f;

        loadA(0, 0);
        loadB(pass, 0, 0);
        asm volatile("cp.async.commit_group;" ::: "memory");
        asm volatile("cp.async.wait_group 0;" ::: "memory");
        __syncthreads();

        for (int c = 0; c < NCH; c++) {
            int buf = c & 1;
            bool more = (c + 1 < NCH);
            if (more) {
                loadA(c + 1, buf ^ 1);
                loadB(pass, c + 1, buf ^ 1);
                asm volatile("cp.async.commit_group;" ::: "memory");
            }

            u32 abase = sb + SOFF_STG + buf * STG_BYTES;
#pragma unroll
            for (int ks = 0; ks < 4; ks++) {
                int g = ks * 2 + lh;
                u32 ah[2][4];
#pragma unroll
                for (int mt = 0; mt < 2; mt++) {
                    int row = warp_m * 32 + mt * 16 + lt;
                    ldm4(ah[mt], abase + AF_OFF + toff(row, g));
                }
#pragma unroll
                for (int nb = 0; nb < 4; nb++) {
                    int nrow = warp_n * 64 + nb * 16 + lt;
                    u32 bh[4];
                    ldm4(bh, abase + BF_OFF + toff(nrow, g));
#pragma unroll
                    for (int mt = 0; mt < 2; mt++)
#pragma unroll
                        for (int s = 0; s < 2; s++)
                            mma16816(acc[mt][nb * 2 + s], ah[mt],
                                     bh[s], bh[s + 2]);
                }
            }
            asm volatile("cp.async.wait_group 0;" ::: "memory");
            __syncthreads();
        }

        // epilogue: q += relu(acc * rinv + b2) * Wq for this pass's 256 n
#pragma unroll
        for (int mt = 0; mt < 2; mt++) {
            int rlo = warp_m * 32 + mt * 16 + (lane >> 2);
            float rv0 = rinvs[rlo], rv1 = rinvs[rlo + 8];
#pragma unroll
            for (int nt = 0; nt < 8; nt++) {
                int n = pass * 256 + warp_n * 64 + nt * 8 + (lane & 3) * 2;
                float bb0 = b2s[n], bb1 = b2s[n + 1];
                float w0 = wqs[n], w1 = wqs[n + 1];
                const float* cc = acc[mt][nt];
                qacc[mt * 2 + 0] += fmaxf(fmaf(cc[0], rv0, bb0), 0.f) * w0 +
                                    fmaxf(fmaf(cc[1], rv0, bb1), 0.f) * w1;
                qacc[mt * 2 + 1] += fmaxf(fmaf(cc[2], rv1, bb0), 0.f) * w0 +
                                    fmaxf(fmaf(cc[3], rv1, bb1), 0.f) * w1;
            }
        }
    }

    // reduce q over the 4 lanes of each quad
#pragma unroll
    for (int off = 1; off <= 2; off <<= 1)
#pragma unroll
        for (int i = 0; i < 4; i++)
            qacc[i] += __shfl_xor_sync(0xffffffffu, qacc[i], off);

    __syncthreads();
    if ((lane & 3) == 0) {
#pragma unroll
        for (int mt = 0; mt < 2; mt++)
#pragma unroll
            for (int hh = 0; hh < 2; hh++) {
                int row = warp_m * 32 + mt * 16 + hh * 8 + (lane >> 2);
                sss[row * 4 + warp_n] = qacc[mt * 2 + hh];
            }
    }
    __syncthreads();
    if (tid < 64)
        out[r0 + tid] = sss[tid * 4] + sss[tid * 4 + 1] +
                        sss[tid * 4 + 2] + sss[tid * 4 + 3] + __ldg(bq);
}

// ---------------------------------------------------------------------------
extern "C" void kernel_launch(void* const* d_in, const int* in_sizes, int n_in,
                              void* d_out, int out_size) {
    const float* states = (const float*)d_in[0];
    const float* W1     = (const float*)d_in[1];
    const float* b1     = (const float*)d_in[2];
    const float* W2     = (const float*)d_in[3];
    const float* b2     = (const float*)d_in[4];
    const float* Wq     = (const float*)d_in[5];
    const float* bq     = (const float*)d_in[6];
    float* out = (float*)d_out;

    cudaFuncSetAttribute((const void*)k_main,
                         cudaFuncAttributeMaxDynamicSharedMemorySize, SMEM_TOTAL);

    k_invn<<<Bd / 8, 256>>>(states);
    k_prep<<<(Ad * H1d + H2d * H1d + 255) / 256, 256>>>(W1, W2);
    k_gemmG<<<(Bd / 128) * (H1d / 128), 256>>>(states, W1, b1);
    k_genA<<<NROWS / 8, 256>>>();
    k_main<<<Bd, 256, SMEM_TOTAL>>>(b2, Wq, bq, out);
}